// round 15
// baseline (speedup 1.0000x reference)
#include <cuda_runtime.h>
#include <cstdint>

// SparseLinear: out[b,k] = dot(embed[b,:], weight[shortlist[b,k],:]) + bias[shortlist[b,k]]
// B=256, K=500, D=512, L=262144  (shortlist buffer is int32)
//
// R12 post-mortem: 41.4us, DRAM 70.6%. Pipeline depth was fine; the losses
// were transients: per-warp drain (4 of 8 iters), per-block startup (serial
// index DRAM load), and 4.6-wave quantization. R14: SPLITS=3 -> 768 blocks =
// ONE fully-resident wave (6 blocks/SM), 42 rows per warp. Startup happens
// once, drain is 4/42 iters, no wave boundaries. Indices + biases for the
// whole block staged in smem at startup (frees the per-warp register arrays).

#define B_DIM 256
#define K_DIM 500
#define D_DIM 512
#define SPLITS 3
#define K_PER_BLOCK ((K_DIM + SPLITS - 1) / SPLITS)   // 167
#define THREADS 128
#define WARPS (THREADS / 32)                          // 4
#define STAGES 4
#define ROW_F4 (D_DIM / 4)                            // 128 float4 per row

__device__ __forceinline__ void cp_async16(uint32_t saddr, const void* gaddr) {
    asm volatile("cp.async.cg.shared.global [%0], [%1], 16;\n"
                 :: "r"(saddr), "l"(gaddr) : "memory");
}
__device__ __forceinline__ void cp_commit() {
    asm volatile("cp.async.commit_group;\n" ::: "memory");
}
template <int N>
__device__ __forceinline__ void cp_wait() {
    asm volatile("cp.async.wait_group %0;\n" :: "n"(N) : "memory");
}

__global__ __launch_bounds__(THREADS)
void sparse_linear_kernel(const float* __restrict__ embed,
                          const int* __restrict__ shortlist,
                          const float* __restrict__ weight,
                          const float* __restrict__ bias,
                          float* __restrict__ out)
{
    __shared__ float4 s_embed[ROW_F4];                    // 2 KB
    __shared__ float4 s_rows[WARPS][STAGES][ROW_F4];      // 32 KB
    __shared__ int    s_idx[K_PER_BLOCK];                 // 668 B
    __shared__ float  s_bias[K_PER_BLOCK];                // 668 B

    const int b    = blockIdx.x;
    const int tid  = threadIdx.x;
    const int warp = tid >> 5;
    const int lane = tid & 31;

    const int k_begin = blockIdx.y * K_PER_BLOCK;
    int kcount = K_DIM - k_begin;
    if (kcount > K_PER_BLOCK) kcount = K_PER_BLOCK;

    // ---- One-time startup (amortized over 42 rows/warp, concurrent in all
    // 768 resident blocks): stage this block's indices + gathered biases.
    const int* sl_row = shortlist + (size_t)b * K_DIM + k_begin;
    for (int t = tid; t < kcount; t += THREADS) {
        const int ii = __ldg(sl_row + t);
        s_idx[t]  = ii;
        s_bias[t] = __ldg(bias + ii);
    }
    const float4* embed_row = reinterpret_cast<const float4*>(embed + (size_t)b * D_DIM);
    s_embed[tid] = embed_row[tid];           // exactly 128 threads / 128 float4
    __syncthreads();

    // Lane-invariant embed slice in registers
    const float4 e0 = s_embed[lane +  0];
    const float4 e1 = s_embed[lane + 32];
    const float4 e2 = s_embed[lane + 64];
    const float4 e3 = s_embed[lane + 96];

    // ---- Prologue: fill the per-warp 4-deep ring (one commit group per stage;
    // empty commits keep group counting aligned).
    #pragma unroll
    for (int s = 0; s < STAGES; s++) {
        const int rel = warp + s * WARPS;
        if (rel < kcount) {
            const float4* wrow =
                reinterpret_cast<const float4*>(weight + (size_t)s_idx[rel] * D_DIM);
            const uint32_t sb =
                (uint32_t)__cvta_generic_to_shared(&s_rows[warp][s][0]);
            cp_async16(sb + (uint32_t)(lane +  0) * 16, wrow + lane +  0);
            cp_async16(sb + (uint32_t)(lane + 32) * 16, wrow + lane + 32);
            cp_async16(sb + (uint32_t)(lane + 64) * 16, wrow + lane + 64);
            cp_async16(sb + (uint32_t)(lane + 96) * 16, wrow + lane + 96);
        }
        cp_commit();
    }

    // ---- Main loop: ~42 rows per warp. Consume row rel (stage i&3), refill
    // that stage with row rel + STAGES*WARPS, reduce, store.
    int i = 0;
    for (int rel = warp; rel < kcount; rel += WARPS, i++) {
        cp_wait<STAGES - 1>();               // this row's group has landed
        const int st = i & (STAGES - 1);

        // Each lane reads exactly the 16B slots it cp.async'd (no cross-lane dep).
        const float4 w0 = s_rows[warp][st][lane +  0];
        const float4 w1 = s_rows[warp][st][lane + 32];
        const float4 w2 = s_rows[warp][st][lane + 64];
        const float4 w3 = s_rows[warp][st][lane + 96];

        float sum = w0.x * e0.x + w0.y * e0.y + w0.z * e0.z + w0.w * e0.w;
        sum      += w1.x * e1.x + w1.y * e1.y + w1.z * e1.z + w1.w * e1.w;
        sum      += w2.x * e2.x + w2.y * e2.y + w2.z * e2.z + w2.w * e2.w;
        sum      += w3.x * e3.x + w3.y * e3.y + w3.z * e3.z + w3.w * e3.w;

        // Refill this stage (issued before the serial shfl chain so the loads
        // overlap it; the FMAs above already consumed the LDS data).
        const int reln = rel + STAGES * WARPS;
        if (reln < kcount) {
            const float4* wrow =
                reinterpret_cast<const float4*>(weight + (size_t)s_idx[reln] * D_DIM);
            const uint32_t sb =
                (uint32_t)__cvta_generic_to_shared(&s_rows[warp][st][0]);
            cp_async16(sb + (uint32_t)(lane +  0) * 16, wrow + lane +  0);
            cp_async16(sb + (uint32_t)(lane + 32) * 16, wrow + lane + 32);
            cp_async16(sb + (uint32_t)(lane + 64) * 16, wrow + lane + 64);
            cp_async16(sb + (uint32_t)(lane + 96) * 16, wrow + lane + 96);
        }
        cp_commit();

        // Warp butterfly reduction overlaps the in-flight cp.asyncs
        #pragma unroll
        for (int off = 16; off > 0; off >>= 1)
            sum += __shfl_xor_sync(0xFFFFFFFFu, sum, off);

        if (lane == 0)
            out[(size_t)b * K_DIM + k_begin + rel] = sum + s_bias[rel];
    }
}

extern "C" void kernel_launch(void* const* d_in, const int* in_sizes, int n_in,
                              void* d_out, int out_size)
{
    const float* embed     = (const float*)d_in[0];  // [B, D] f32
    const int*   shortlist = (const int*)d_in[1];    // [B, K] i32
    const float* weight    = (const float*)d_in[2];  // [L, D] f32
    const float* bias      = (const float*)d_in[3];  // [L, 1] f32
    float*       out       = (float*)d_out;          // [B, K] f32

    dim3 grid(B_DIM, SPLITS);
    sparse_linear_kernel<<<grid, THREADS>>>(embed, shortlist, weight, bias, out);
}

// round 16
// speedup vs baseline: 1.0844x; 1.0844x over previous
#include <cuda_runtime.h>
#include <cstdint>

// SparseLinear: out[b,k] = dot(embed[b,:], weight[shortlist[b,k],:]) + bias[shortlist[b,k]]
// B=256, K=500, D=512, L=262144  (shortlist buffer is int32)
//
// R14 post-mortem: single-wave long-stream REGRESSED (DRAM 65%): equal-length
// blocks with no rebalancing expose per-CTA latency spread; multi-wave small
// blocks overlap transients by construction. R15 = R12 shape (multi-wave,
// cp.async smem ring) with: STAGES 4->3 (smem 26KB -> 8 blocks/SM, 32 warps),
// idx/bias staged in block smem (regs ~52 so RF also allows 8 blocks/SM),
// SPLITS 14 -> 3584 blocks = 3.03 waves at 1184 resident (near-zero partial
// wave tail).

#define B_DIM 256
#define K_DIM 500
#define D_DIM 512
#define SPLITS 14
#define K_PER_BLOCK ((K_DIM + SPLITS - 1) / SPLITS)   // 36
#define THREADS 128
#define WARPS (THREADS / 32)                          // 4
#define STAGES 3
#define ROW_F4 (D_DIM / 4)                            // 128 float4 per row

__device__ __forceinline__ void cp_async16(uint32_t saddr, const void* gaddr) {
    asm volatile("cp.async.cg.shared.global [%0], [%1], 16;\n"
                 :: "r"(saddr), "l"(gaddr) : "memory");
}
__device__ __forceinline__ void cp_commit() {
    asm volatile("cp.async.commit_group;\n" ::: "memory");
}
template <int N>
__device__ __forceinline__ void cp_wait() {
    asm volatile("cp.async.wait_group %0;\n" :: "n"(N) : "memory");
}

__global__ __launch_bounds__(THREADS)
void sparse_linear_kernel(const float* __restrict__ embed,
                          const int* __restrict__ shortlist,
                          const float* __restrict__ weight,
                          const float* __restrict__ bias,
                          float* __restrict__ out)
{
    __shared__ float4 s_embed[ROW_F4];                    // 2 KB
    __shared__ float4 s_rows[WARPS][STAGES][ROW_F4];      // 24 KB
    __shared__ int    s_idx[K_PER_BLOCK];
    __shared__ float  s_bias[K_PER_BLOCK];

    const int b    = blockIdx.x;
    const int tid  = threadIdx.x;
    const int warp = tid >> 5;
    const int lane = tid & 31;

    const int k_begin = blockIdx.y * K_PER_BLOCK;
    int kcount = K_DIM - k_begin;
    if (kcount > K_PER_BLOCK) kcount = K_PER_BLOCK;

    // Stage this block's indices + gathered biases + embed row (one time).
    const int* sl_row = shortlist + (size_t)b * K_DIM + k_begin;
    if (tid < kcount) {
        const int ii = __ldg(sl_row + tid);
        s_idx[tid]  = ii;
        s_bias[tid] = __ldg(bias + ii);
    }
    const float4* embed_row = reinterpret_cast<const float4*>(embed + (size_t)b * D_DIM);
    s_embed[tid] = embed_row[tid];           // 128 threads / 128 float4
    __syncthreads();

    // Lane-invariant embed slice in registers
    const float4 e0 = s_embed[lane +  0];
    const float4 e1 = s_embed[lane + 32];
    const float4 e2 = s_embed[lane + 64];
    const float4 e3 = s_embed[lane + 96];

    // Prologue: fill the per-warp 3-deep ring (one commit group per stage;
    // empty commits keep the group count aligned for short blocks).
    #pragma unroll
    for (int s = 0; s < STAGES; s++) {
        const int rel = warp + s * WARPS;
        if (rel < kcount) {
            const float4* wrow =
                reinterpret_cast<const float4*>(weight + (size_t)s_idx[rel] * D_DIM);
            const uint32_t sb =
                (uint32_t)__cvta_generic_to_shared(&s_rows[warp][s][0]);
            cp_async16(sb + (uint32_t)(lane +  0) * 16, wrow + lane +  0);
            cp_async16(sb + (uint32_t)(lane + 32) * 16, wrow + lane + 32);
            cp_async16(sb + (uint32_t)(lane + 64) * 16, wrow + lane + 64);
            cp_async16(sb + (uint32_t)(lane + 96) * 16, wrow + lane + 96);
        }
        cp_commit();
    }

    // Main loop: consume row rel (stage i%3), refill with row rel+STAGES*WARPS.
    int i = 0;
    int st = 0;
    for (int rel = warp; rel < kcount; rel += WARPS, i++) {
        cp_wait<STAGES - 1>();               // this row's group has landed

        // Each lane reads exactly the 16B slots it cp.async'd (no cross-lane dep).
        const float4 w0 = s_rows[warp][st][lane +  0];
        const float4 w1 = s_rows[warp][st][lane + 32];
        const float4 w2 = s_rows[warp][st][lane + 64];
        const float4 w3 = s_rows[warp][st][lane + 96];

        float sum = w0.x * e0.x + w0.y * e0.y + w0.z * e0.z + w0.w * e0.w;
        sum      += w1.x * e1.x + w1.y * e1.y + w1.z * e1.z + w1.w * e1.w;
        sum      += w2.x * e2.x + w2.y * e2.y + w2.z * e2.z + w2.w * e2.w;
        sum      += w3.x * e3.x + w3.y * e3.y + w3.z * e3.z + w3.w * e3.w;

        // Refill this stage (issued before the serial shfl chain so the loads
        // overlap it; the FMAs above already consumed the LDS data).
        const int reln = rel + STAGES * WARPS;
        if (reln < kcount) {
            const float4* wrow =
                reinterpret_cast<const float4*>(weight + (size_t)s_idx[reln] * D_DIM);
            const uint32_t sb =
                (uint32_t)__cvta_generic_to_shared(&s_rows[warp][st][0]);
            cp_async16(sb + (uint32_t)(lane +  0) * 16, wrow + lane +  0);
            cp_async16(sb + (uint32_t)(lane + 32) * 16, wrow + lane + 32);
            cp_async16(sb + (uint32_t)(lane + 64) * 16, wrow + lane + 64);
            cp_async16(sb + (uint32_t)(lane + 96) * 16, wrow + lane + 96);
        }
        cp_commit();

        // Warp butterfly reduction overlaps the in-flight cp.asyncs
        #pragma unroll
        for (int off = 16; off > 0; off >>= 1)
            sum += __shfl_xor_sync(0xFFFFFFFFu, sum, off);

        if (lane == 0)
            out[(size_t)b * K_DIM + k_begin + rel] = sum + s_bias[rel];

        st = (st == STAGES - 1) ? 0 : st + 1;
    }
}

extern "C" void kernel_launch(void* const* d_in, const int* in_sizes, int n_in,
                              void* d_out, int out_size)
{
    const float* embed     = (const float*)d_in[0];  // [B, D] f32
    const int*   shortlist = (const int*)d_in[1];    // [B, K] i32
    const float* weight    = (const float*)d_in[2];  // [L, D] f32
    const float* bias      = (const float*)d_in[3];  // [L, 1] f32
    float*       out       = (float*)d_out;          // [B, K] f32

    dim3 grid(B_DIM, SPLITS);
    sparse_linear_kernel<<<grid, THREADS>>>(embed, shortlist, weight, bias, out);
}